// round 4
// baseline (speedup 1.0000x reference)
#include <cuda_runtime.h>
#include <cuda_fp16.h>

#define NUx 200000
#define NIx 100000
#define Dx  64
#define Ex  2000000
#define Bx  8192
#define EPSx 1e-12f

#define SB 256
#define SI 8                 // 2048 elements per scan block
#define NW (SB/32)

// ---- static device scratch (no allocation allowed) ----
__device__ int g_deg_u[NUx];
__device__ int g_deg_i[NIx];
__device__ float g_rsd_u[NUx];   // rsqrt(deg)
__device__ float g_rsd_i[NIx];
__device__ int g_off_u[NUx];
__device__ int g_off_i[NIx];
__device__ int g_cur_u[NUx];
__device__ int g_cur_i[NIx];
__device__ int g_bsum_u[128];
__device__ int g_bsum_i[128];
__device__ int g_adj_u[Ex];      // per-user neighbor items
__device__ int g_adj_i[Ex];      // per-item neighbor users

// fp16 feature storage: rows of 8 uint4 (64 halves = 128B)
__device__ __align__(256) uint4 g_uf16[(size_t)NUx * 8];
__device__ __align__(256) uint4 g_if16[(size_t)NIx * 8];
__device__ __align__(256) uint4 g_hu16[3][(size_t)NUx * 8];
__device__ __align__(256) uint4 g_hi16[3][(size_t)NIx * 8];

// ---- degree histogram (int) ----
__global__ void k_deg(const int* __restrict__ eu, const int* __restrict__ ei) {
    int t = blockIdx.x * blockDim.x + threadIdx.x;
    if (t < Ex) {
        atomicAdd(&g_deg_u[eu[t]], 1);
        atomicAdd(&g_deg_i[ei[t]], 1);
    }
}

// ---- per-node inverse sqrt degree ----
__global__ void k_rsd() {
    int t = blockIdx.x * blockDim.x + threadIdx.x;
    if (t < NUx) g_rsd_u[t] = rsqrtf((float)max(g_deg_u[t], 1));
    if (t < NIx) g_rsd_i[t] = rsqrtf((float)max(g_deg_i[t], 1));
}

// ---- exclusive scan, stage 1: per-block scan + block sums ----
__global__ void k_scan_blocks(const int* __restrict__ in, int* __restrict__ out,
                              int* __restrict__ bsum, int n) {
    __shared__ int warp_tot[NW];
    int lane = threadIdx.x & 31, wid = threadIdx.x >> 5;
    int base = blockIdx.x * (SB * SI) + threadIdx.x * SI;

    int v[SI];
    int s = 0;
    #pragma unroll
    for (int k = 0; k < SI; ++k) {
        int idx = base + k;
        v[k] = (idx < n) ? in[idx] : 0;
        s += v[k];
    }
    int ps = s;
    #pragma unroll
    for (int o = 1; o < 32; o <<= 1) {
        int t = __shfl_up_sync(0xffffffffu, ps, o);
        if (lane >= o) ps += t;
    }
    if (lane == 31) warp_tot[wid] = ps;
    __syncthreads();
    if (wid == 0) {
        int wt = (lane < NW) ? warp_tot[lane] : 0;
        int wps = wt;
        #pragma unroll
        for (int o = 1; o < NW; o <<= 1) {
            int t = __shfl_up_sync(0xffffffffu, wps, o);
            if (lane >= o) wps += t;
        }
        if (lane < NW) warp_tot[lane] = wps - wt;
    }
    __syncthreads();
    int excl = warp_tot[wid] + (ps - s);
    int run = excl;
    #pragma unroll
    for (int k = 0; k < SI; ++k) {
        int idx = base + k;
        if (idx < n) out[idx] = run;
        run += v[k];
    }
    if (threadIdx.x == SB - 1) bsum[blockIdx.x] = excl + s;
}

// ---- exclusive scan of both block-sum arrays in one launch ----
__global__ void k_scan_small2(int* __restrict__ bu, int nu_,
                              int* __restrict__ bi, int ni_) {
    int* b = blockIdx.x ? bi : bu;
    int n  = blockIdx.x ? ni_ : nu_;
    __shared__ int wt[4];
    int tid = threadIdx.x;
    int lane = tid & 31, wid = tid >> 5;
    int v = (tid < n) ? b[tid] : 0;
    int ps = v;
    #pragma unroll
    for (int o = 1; o < 32; o <<= 1) {
        int t = __shfl_up_sync(0xffffffffu, ps, o);
        if (lane >= o) ps += t;
    }
    if (lane == 31) wt[wid] = ps;
    __syncthreads();
    if (tid == 0) {
        int r = 0;
        #pragma unroll
        for (int k = 0; k < 4; ++k) { int t = wt[k]; wt[k] = r; r += t; }
    }
    __syncthreads();
    if (tid < n) b[tid] = wt[wid] + ps - v;
}

// ---- scan stage 3: add block offsets; also init cursor copy ----
__global__ void k_scan_add(int* __restrict__ out, int* __restrict__ cur,
                           const int* __restrict__ bsum, int n) {
    int base = blockIdx.x * (SB * SI) + threadIdx.x * SI;
    int add = bsum[blockIdx.x];
    #pragma unroll
    for (int k = 0; k < SI; ++k) {
        int idx = base + k;
        if (idx < n) {
            int val = out[idx] + add;
            out[idx] = val;
            cur[idx] = val;
        }
    }
}

// ---- counting-sort fill of both adjacency lists (ids only) ----
__global__ void k_fill(const int* __restrict__ eu, const int* __restrict__ ei) {
    int e = blockIdx.x * blockDim.x + threadIdx.x;
    if (e >= Ex) return;
    int u = eu[e], i = ei[e];
    int pu = atomicAdd(&g_cur_u[u], 1);
    g_adj_u[pu] = i;
    int pi = atomicAdd(&g_cur_i[i], 1);
    g_adj_i[pi] = u;
}

// ---- convert fp32 inputs to fp16 staging ----
__global__ void k_cvt(const float* __restrict__ uf, const float* __restrict__ itf) {
    int t = blockIdx.x * blockDim.x + threadIdx.x;
    const int NT = NUx * 8;   // uint4 elements for users
    if (t < NT) {
        const float4* s = (const float4*)uf;
        float4 a = s[t * 2], b = s[t * 2 + 1];
        __half2 h0 = __float22half2_rn(make_float2(a.x, a.y));
        __half2 h1 = __float22half2_rn(make_float2(a.z, a.w));
        __half2 h2 = __float22half2_rn(make_float2(b.x, b.y));
        __half2 h3 = __float22half2_rn(make_float2(b.z, b.w));
        g_uf16[t] = make_uint4(*(unsigned*)&h0, *(unsigned*)&h1, *(unsigned*)&h2, *(unsigned*)&h3);
    } else if (t < NT + NIx * 8) {
        int s2 = t - NT;
        const float4* s = (const float4*)itf;
        float4 a = s[s2 * 2], b = s[s2 * 2 + 1];
        __half2 h0 = __float22half2_rn(make_float2(a.x, a.y));
        __half2 h1 = __float22half2_rn(make_float2(a.z, a.w));
        __half2 h2 = __float22half2_rn(make_float2(b.x, b.y));
        __half2 h3 = __float22half2_rn(make_float2(b.z, b.w));
        g_if16[s2] = make_uint4(*(unsigned*)&h0, *(unsigned*)&h1, *(unsigned*)&h2, *(unsigned*)&h3);
    }
}

// ---- merged both-direction gather-aggregate + fused L2-normalize ----
// warp per dest row; lane = (g = lane>>3 neighbor subgroup, c = lane&7 col chunk)
// Destination degree factor cancels under L2 normalization and is omitted.
__global__ void k_agg(const uint4* __restrict__ srcU,
                      const uint4* __restrict__ srcI,
                      uint4* __restrict__ houtU,
                      uint4* __restrict__ houtI) {
    __shared__ int   sid[NW][32];
    __shared__ float swt[NW][32];
    int gw = (blockIdx.x * blockDim.x + threadIdx.x) >> 5;
    int lane = threadIdx.x & 31;
    int wid = threadIdx.x >> 5;
    if (gw >= NIx + NUx) return;
    int g = lane >> 3, c = lane & 7;

    const uint4* src;
    uint4* hout;
    const int* adj;
    const float* rsd;
    int beg, end, row;
    if (gw < NIx) {
        row = gw;
        src = srcU; hout = houtI; adj = g_adj_i; rsd = g_rsd_u;
        beg = g_off_i[row];
        end = (row + 1 < NIx) ? g_off_i[row + 1] : Ex;
    } else {
        row = gw - NIx;
        src = srcI; hout = houtU; adj = g_adj_u; rsd = g_rsd_i;
        beg = g_off_u[row];
        end = (row + 1 < NUx) ? g_off_u[row + 1] : Ex;
    }

    float acc[8];
    #pragma unroll
    for (int k = 0; k < 8; ++k) acc[k] = 0.f;

    for (int p = beg; p < end; p += 32) {
        int idx = p + lane;
        int id = 0; float w = 0.f;
        if (idx < end) { id = adj[idx]; w = rsd[id]; }
        sid[wid][lane] = id;
        swt[wid][lane] = w;
        __syncwarp();
        int iters = (min(end - p, 32) + 3) >> 2;
        #pragma unroll 2
        for (int it = 0; it < iters; ++it) {
            int j = it * 4 + g;
            int nid = sid[wid][j];
            float nw = swt[wid][j];
            uint4 raw = __ldg(&src[(size_t)nid * 8 + c]);
            float2 f0 = __half22float2(*(__half2*)&raw.x);
            float2 f1 = __half22float2(*(__half2*)&raw.y);
            float2 f2 = __half22float2(*(__half2*)&raw.z);
            float2 f3 = __half22float2(*(__half2*)&raw.w);
            acc[0] += nw * f0.x; acc[1] += nw * f0.y;
            acc[2] += nw * f1.x; acc[3] += nw * f1.y;
            acc[4] += nw * f2.x; acc[5] += nw * f2.y;
            acc[6] += nw * f3.x; acc[7] += nw * f3.y;
        }
        __syncwarp();
    }

    // reduce over the 4 neighbor subgroups (lane bits 3,4)
    #pragma unroll
    for (int k = 0; k < 8; ++k) {
        acc[k] += __shfl_xor_sync(0xffffffffu, acc[k], 8);
        acc[k] += __shfl_xor_sync(0xffffffffu, acc[k], 16);
    }
    // sum of squares over the 8 column chunks (lane bits 0..2)
    float s = 0.f;
    #pragma unroll
    for (int k = 0; k < 8; ++k) s += acc[k] * acc[k];
    s += __shfl_xor_sync(0xffffffffu, s, 1);
    s += __shfl_xor_sync(0xffffffffu, s, 2);
    s += __shfl_xor_sync(0xffffffffu, s, 4);
    float inv = 1.0f / fmaxf(sqrtf(s), EPSx);

    if (g == 0) {
        __half2 h0 = __float22half2_rn(make_float2(acc[0] * inv, acc[1] * inv));
        __half2 h1 = __float22half2_rn(make_float2(acc[2] * inv, acc[3] * inv));
        __half2 h2 = __float22half2_rn(make_float2(acc[4] * inv, acc[5] * inv));
        __half2 h3 = __float22half2_rn(make_float2(acc[6] * inv, acc[7] * inv));
        hout[(size_t)row * 8 + c] =
            make_uint4(*(unsigned*)&h0, *(unsigned*)&h1, *(unsigned*)&h2, *(unsigned*)&h3);
    }
}

// ---- final gather: e = f + h0 + h1/2 + h2/3 at sampled rows ----
__global__ void k_out(const float* __restrict__ uf, const float* __restrict__ itf,
                      const int* __restrict__ users, const int* __restrict__ pos,
                      const int* __restrict__ neg, float* __restrict__ out) {
    unsigned t = blockIdx.x * blockDim.x + threadIdx.x;
    unsigned r = t >> 3;
    unsigned lane = t & 7u;          // 8 lanes x 8 cols = 64
    if (r >= 3u * Bx) return;
    unsigned grp = r / Bx, idx = r % Bx;

    const float* base;
    const uint4 *h0, *h1, *h2;
    size_t row;
    if (grp == 0) {
        row = (size_t)users[idx];
        base = uf + row * Dx;
        h0 = g_hu16[0] + row * 8; h1 = g_hu16[1] + row * 8; h2 = g_hu16[2] + row * 8;
    } else {
        row = (size_t)((grp == 1) ? pos[idx] : neg[idx]);
        base = itf + row * Dx;
        h0 = g_hi16[0] + row * 8; h1 = g_hi16[1] + row * 8; h2 = g_hi16[2] + row * 8;
    }

    float4 fa = *(const float4*)(base + lane * 8);
    float4 fb = *(const float4*)(base + lane * 8 + 4);
    uint4 r0 = h0[lane], r1 = h1[lane], r2 = h2[lane];

    const float c1 = 0.5f, c2 = 1.0f / 3.0f;
    #define ACCUM(fv, comp, word, half_sel) do {                              \
        float2 x0 = __half22float2(*(__half2*)&r0.word);                      \
        float2 x1 = __half22float2(*(__half2*)&r1.word);                      \
        float2 x2 = __half22float2(*(__half2*)&r2.word);                      \
        fv.comp   += x0.x + c1 * x1.x + c2 * x2.x;                            \
        fv.half_sel += x0.y + c1 * x1.y + c2 * x2.y;                          \
    } while (0)
    ACCUM(fa, x, x, y);
    ACCUM(fa, z, y, w);
    ACCUM(fb, x, z, y);
    ACCUM(fb, z, w, w);
    #undef ACCUM

    float* o = out + (size_t)r * Dx + lane * 8;
    *(float4*)o = fa;
    *(float4*)(o + 4) = fb;
}

extern "C" void kernel_launch(void* const* d_in, const int* in_sizes, int n_in,
                              void* d_out, int out_size) {
    const float* uf  = (const float*)d_in[0];
    const float* itf = (const float*)d_in[1];
    const int*   eu  = (const int*)d_in[2];
    const int*   ei  = (const int*)d_in[3];
    const int*   usr = (const int*)d_in[4];
    const int*   pos = (const int*)d_in[5];
    const int*   neg = (const int*)d_in[6];
    float* out = (float*)d_out;

    void *p_deg_u, *p_deg_i, *p_off_u, *p_off_i, *p_cur_u, *p_cur_i;
    void *p_bsum_u, *p_bsum_i;
    void *p_uf16, *p_if16, *p_hu[3], *p_hi[3];
    cudaGetSymbolAddress(&p_deg_u, g_deg_u);
    cudaGetSymbolAddress(&p_deg_i, g_deg_i);
    cudaGetSymbolAddress(&p_off_u, g_off_u);
    cudaGetSymbolAddress(&p_off_i, g_off_i);
    cudaGetSymbolAddress(&p_cur_u, g_cur_u);
    cudaGetSymbolAddress(&p_cur_i, g_cur_i);
    cudaGetSymbolAddress(&p_bsum_u, g_bsum_u);
    cudaGetSymbolAddress(&p_bsum_i, g_bsum_i);
    cudaGetSymbolAddress(&p_uf16, g_uf16);
    cudaGetSymbolAddress(&p_if16, g_if16);
    {
        void* tmp;
        cudaGetSymbolAddress(&tmp, g_hu16);
        for (int k = 0; k < 3; ++k) p_hu[k] = (char*)tmp + (size_t)k * NUx * 8 * sizeof(uint4);
        cudaGetSymbolAddress(&tmp, g_hi16);
        for (int k = 0; k < 3; ++k) p_hi[k] = (char*)tmp + (size_t)k * NIx * 8 * sizeof(uint4);
    }

    const int scanb_u = (NUx + SB * SI - 1) / (SB * SI);   // 98
    const int scanb_i = (NIx + SB * SI - 1) / (SB * SI);   // 49

    // ---- CSR build + fp16 input staging ----
    cudaMemsetAsync(p_deg_u, 0, NUx * sizeof(int));
    cudaMemsetAsync(p_deg_i, 0, NIx * sizeof(int));
    k_deg<<<(Ex + 255) / 256, 256>>>(eu, ei);
    k_cvt<<<((NUx + NIx) * 8 + 255) / 256, 256>>>(uf, itf);
    k_rsd<<<(NUx + 255) / 256, 256>>>();
    k_scan_blocks<<<scanb_u, SB>>>((const int*)p_deg_u, (int*)p_off_u, (int*)p_bsum_u, NUx);
    k_scan_blocks<<<scanb_i, SB>>>((const int*)p_deg_i, (int*)p_off_i, (int*)p_bsum_i, NIx);
    k_scan_small2<<<2, 128>>>((int*)p_bsum_u, scanb_u, (int*)p_bsum_i, scanb_i);
    k_scan_add<<<scanb_u, SB>>>((int*)p_off_u, (int*)p_cur_u, (const int*)p_bsum_u, NUx);
    k_scan_add<<<scanb_i, SB>>>((int*)p_off_i, (int*)p_cur_i, (const int*)p_bsum_i, NIx);
    k_fill<<<(Ex + 255) / 256, 256>>>(eu, ei);

    const unsigned gagg = (unsigned)(((size_t)(NUx + NIx) * 32 + 255) / 256);

    // ---- 3 propagation layers (both directions merged per launch) ----
    k_agg<<<gagg, 256>>>((const uint4*)p_uf16, (const uint4*)p_if16,
                         (uint4*)p_hu[0], (uint4*)p_hi[0]);
    k_agg<<<gagg, 256>>>((const uint4*)p_hu[0], (const uint4*)p_hi[0],
                         (uint4*)p_hu[1], (uint4*)p_hi[1]);
    k_agg<<<gagg, 256>>>((const uint4*)p_hu[1], (const uint4*)p_hi[1],
                         (uint4*)p_hu[2], (uint4*)p_hi[2]);

    // ---- output gather (e computed on the fly) ----
    k_out<<<(3 * Bx * 8 + 255) / 256, 256>>>(uf, itf, usr, pos, neg, out);
}